// round 1
// baseline (speedup 1.0000x reference)
#include <cuda_runtime.h>

// CubePadding: x [B=4, 6, C=64, H=128, W=128] f32 -> out [B, 6, C, 132, 132] f32
// P = 2 padding on all sides, halo taken from neighboring cube faces with
// flips/transposes per the reference mapping.

#define Pp 2
#define Bn 4
#define Cn 64
#define Hn 128
#define Wn 128
#define OH 132
#define OW 132

// face ids: 0=back(fb) 1=down(fd) 2=front(ff) 3=left(fl) 4=right(fr) 5=top(ft)

__device__ __forceinline__ void top_map(int f, int i, int j, int& sf, int& sh, int& sw) {
    switch (f) {
        case 0: sf = 5; sh = Pp - 1 - i;  sw = j;           break; // flip_h(ft[:P])
        case 1: sf = 2; sh = Hn - Pp + i; sw = j;           break; // ff[-P:]
        case 2: sf = 5; sh = Hn - Pp + i; sw = j;           break; // ft[-P:]
        case 3: sf = 5; sh = j;           sw = i;           break; // T(ft[:, :P])
        case 4: sf = 5; sh = j;           sw = Wn - 1 - i;  break; // flip_h(T(ft[:, -P:]))
        default: sf = 0; sh = Pp - 1 - i; sw = j;           break; // flip_h(fb[:P])
    }
}

__device__ __forceinline__ void bot_map(int f, int i, int j, int& sf, int& sh, int& sw) {
    switch (f) {
        case 0: sf = 1; sh = Hn - 1 - i;  sw = j;           break; // flip_h(fd[-P:])
        case 1: sf = 0; sh = Hn - 1 - i;  sw = j;           break; // flip_h(fb[-P:])
        case 2: sf = 1; sh = i;           sw = j;           break; // fd[:P]
        case 3: sf = 1; sh = j;           sw = Pp - 1 - i;  break; // flip_h(T(fd[:, :P]))
        case 4: sf = 1; sh = j;           sw = Wn - Pp + i; break; // T(fd[:, -P:])
        default: sf = 2; sh = i;          sw = j;           break; // ff[:P]
    }
}

__device__ __forceinline__ void lft_map(int f, int r, int i, int& sf, int& sh, int& sw) {
    switch (f) {
        case 0: sf = 4; sh = r;           sw = Wn - Pp + i; break; // fr[:, -P:]
        case 1: sf = 3; sh = Hn - 1 - i;  sw = r;           break; // flip_w(T(fl[-P:, :]))
        case 2: sf = 3; sh = r;           sw = Wn - Pp + i; break; // fl[:, -P:]
        case 3: sf = 0; sh = r;           sw = Wn - Pp + i; break; // fb[:, -P:]
        case 4: sf = 2; sh = r;           sw = Wn - Pp + i; break; // ff[:, -P:]
        default: sf = 3; sh = i;          sw = r;           break; // T(fl[:P, :])
    }
}

__device__ __forceinline__ void rgt_map(int f, int r, int i, int& sf, int& sh, int& sw) {
    switch (f) {
        case 0: sf = 3; sh = r;           sw = i;           break; // fl[:, :P]
        case 1: sf = 4; sh = Hn - Pp + i; sw = r;           break; // T(fr[-P:, :])
        case 2: sf = 4; sh = r;           sw = i;           break; // fr[:, :P]
        case 3: sf = 2; sh = r;           sw = i;           break; // ff[:, :P]
        case 4: sf = 0; sh = r;           sw = i;           break; // fb[:, :P]
        default: sf = 4; sh = Pp - 1 - i; sw = r;           break; // flip_w(T(fr[:P, :]))
    }
}

// Full output-coordinate -> source mapping (corners collapse to strip edge cols)
__device__ __forceinline__ void src_map(int f, int ho, int wo, int& sf, int& sh, int& sw) {
    if (wo >= Pp && wo < Pp + Wn) {
        int j = wo - Pp;
        if (ho < Pp)                top_map(f, ho, j, sf, sh, sw);
        else if (ho >= Pp + Hn)     bot_map(f, ho - Pp - Hn, j, sf, sh, sw);
        else { sf = f; sh = ho - Pp; sw = j; }
    } else if (wo < Pp) {
        if (ho < Pp)                top_map(f, ho, 0, sf, sh, sw);          // p_tl = top[:, 0]
        else if (ho >= Pp + Hn)     bot_map(f, ho - Pp - Hn, 0, sf, sh, sw);// p_dl = bot[:, 0]
        else                        lft_map(f, ho - Pp, wo, sf, sh, sw);
    } else {
        if (ho < Pp)                top_map(f, ho, Wn - 1, sf, sh, sw);     // p_tr = top[:, W-1]
        else if (ho >= Pp + Hn)     bot_map(f, ho - Pp - Hn, Wn - 1, sf, sh, sw);
        else                        rgt_map(f, ho - Pp, wo - Pp - Wn, sf, sh, sw);
    }
}

// ---------------------------------------------------------------------------
// Interior: straight row copy, float2 vectorized (out row offset 2 -> 8B aligned)
// ---------------------------------------------------------------------------
__global__ void cube_pad_interior(const float2* __restrict__ x, float2* __restrict__ out) {
    int tid = blockIdx.x * blockDim.x + threadIdx.x;
    const int total = Bn * 6 * Cn * Hn * (Wn / 2);   // 12,582,912
    if (tid >= total) return;
    int j2  = tid & (Wn / 2 - 1);   // 0..63
    int row = tid >> 6;             // g*H + h
    int h   = row & (Hn - 1);
    int g   = row >> 7;             // (b*6+f)*C + c

    long src = (long)g * (Hn * Wn / 2) + h * (Wn / 2) + j2;
    long dst = (long)g * (OH * OW / 2) + (h + Pp) * (OW / 2) + 1 + j2;
    out[dst] = x[src];
}

// ---------------------------------------------------------------------------
// Halo: 1040 elements per face-channel (top/bot bands incl. corners + side bands)
// ---------------------------------------------------------------------------
__global__ void cube_pad_halo(const float* __restrict__ x, float* __restrict__ out) {
    const int HALO = 2 * Pp * OW + 2 * Hn * Pp;      // 528 + 512 = 1040
    int tid = blockIdx.x * blockDim.x + threadIdx.x;
    const int total = Bn * 6 * Cn * HALO;            // 1,597,440
    if (tid >= total) return;

    int k = tid % HALO;
    int g = tid / HALO;
    int b = g / (6 * Cn);
    int f = (g / Cn) % 6;
    int c = g % Cn;

    int ho, wo;
    if (k < Pp * OW) {                               // top band (rows 0..P-1, full width)
        ho = k / OW; wo = k % OW;
    } else if (k < 2 * Pp * OW) {                    // bottom band
        int kk = k - Pp * OW;
        ho = Pp + Hn + kk / OW; wo = kk % OW;
    } else if (k < 2 * Pp * OW + Hn * Pp) {          // left band (middle rows)
        int kk = k - 2 * Pp * OW;
        ho = Pp + kk / Pp; wo = kk % Pp;
    } else {                                         // right band
        int kk = k - 2 * Pp * OW - Hn * Pp;
        ho = Pp + kk / Pp; wo = Pp + Wn + kk % Pp;
    }

    int sf, sh, sw;
    src_map(f, ho, wo, sf, sh, sw);

    long src = ((long)(b * 6 + sf) * Cn + c) * (Hn * Wn) + sh * Wn + sw;
    long dst = (long)g * (OH * OW) + ho * OW + wo;
    out[dst] = x[src];
}

extern "C" void kernel_launch(void* const* d_in, const int* in_sizes, int n_in,
                              void* d_out, int out_size) {
    const float* x = (const float*)d_in[0];
    float* out = (float*)d_out;

    const int nInt = Bn * 6 * Cn * Hn * (Wn / 2);    // float2 elements
    cube_pad_interior<<<(nInt + 255) / 256, 256>>>((const float2*)x, (float2*)out);

    const int nHalo = Bn * 6 * Cn * (2 * Pp * OW + 2 * Hn * Pp);
    cube_pad_halo<<<(nHalo + 255) / 256, 256>>>(x, out);
}

// round 2
// speedup vs baseline: 1.1875x; 1.1875x over previous
#include <cuda_runtime.h>

// CubePadding: x [B=4, 6, C=64, H=128, W=128] f32 -> out [B, 6, C, 132, 132] f32
// Fused single kernel: every thread writes one aligned float4 of the output.
// Full output row = 132 floats = 33 aligned float4s (row offset ≡ 0 mod 4).

#define Pp 2
#define Bn 4
#define Cn 64
#define Hn 128
#define Wn 128
#define OH 132
#define OW 132
#define W4 33                          // float4s per output row
#define NROWS (Bn * 6 * Cn * OH)       // 202752
#define TOTAL4 (NROWS * W4)            // 6,690,816

// face ids: 0=back(fb) 1=down(fd) 2=front(ff) 3=left(fl) 4=right(fr) 5=top(ft)

__device__ __forceinline__ void top_map(int f, int i, int j, int& sf, int& sh, int& sw) {
    switch (f) {
        case 0: sf = 5; sh = Pp - 1 - i;  sw = j;           break; // flip_h(ft[:P])
        case 1: sf = 2; sh = Hn - Pp + i; sw = j;           break; // ff[-P:]
        case 2: sf = 5; sh = Hn - Pp + i; sw = j;           break; // ft[-P:]
        case 3: sf = 5; sh = j;           sw = i;           break; // T(ft[:, :P])
        case 4: sf = 5; sh = j;           sw = Wn - 1 - i;  break; // flip_h(T(ft[:, -P:]))
        default: sf = 0; sh = Pp - 1 - i; sw = j;           break; // flip_h(fb[:P])
    }
}

__device__ __forceinline__ void bot_map(int f, int i, int j, int& sf, int& sh, int& sw) {
    switch (f) {
        case 0: sf = 1; sh = Hn - 1 - i;  sw = j;           break; // flip_h(fd[-P:])
        case 1: sf = 0; sh = Hn - 1 - i;  sw = j;           break; // flip_h(fb[-P:])
        case 2: sf = 1; sh = i;           sw = j;           break; // fd[:P]
        case 3: sf = 1; sh = j;           sw = Pp - 1 - i;  break; // flip_h(T(fd[:, :P]))
        case 4: sf = 1; sh = j;           sw = Wn - Pp + i; break; // T(fd[:, -P:])
        default: sf = 2; sh = i;          sw = j;           break; // ff[:P]
    }
}

__device__ __forceinline__ void lft_map(int f, int r, int i, int& sf, int& sh, int& sw) {
    switch (f) {
        case 0: sf = 4; sh = r;           sw = Wn - Pp + i; break; // fr[:, -P:]
        case 1: sf = 3; sh = Hn - 1 - i;  sw = r;           break; // flip_w(T(fl[-P:, :]))
        case 2: sf = 3; sh = r;           sw = Wn - Pp + i; break; // fl[:, -P:]
        case 3: sf = 0; sh = r;           sw = Wn - Pp + i; break; // fb[:, -P:]
        case 4: sf = 2; sh = r;           sw = Wn - Pp + i; break; // ff[:, -P:]
        default: sf = 3; sh = i;          sw = r;           break; // T(fl[:P, :])
    }
}

__device__ __forceinline__ void rgt_map(int f, int r, int i, int& sf, int& sh, int& sw) {
    switch (f) {
        case 0: sf = 3; sh = r;           sw = i;           break; // fl[:, :P]
        case 1: sf = 4; sh = Hn - Pp + i; sw = r;           break; // T(fr[-P:, :])
        case 2: sf = 4; sh = r;           sw = i;           break; // fr[:, :P]
        case 3: sf = 2; sh = r;           sw = i;           break; // ff[:, :P]
        case 4: sf = 0; sh = r;           sw = i;           break; // fb[:, :P]
        default: sf = 4; sh = Pp - 1 - i; sw = r;           break; // flip_w(T(fr[:P, :]))
    }
}

// Output coord (f, ho, wo) -> source (sf, sh, sw). Corners collapse to the
// top/bot strip's edge column (reference tiles that column across the pad).
__device__ __forceinline__ void src_map(int f, int ho, int wo, int& sf, int& sh, int& sw) {
    if (wo >= Pp && wo < Pp + Wn) {
        int j = wo - Pp;
        if (ho < Pp)                top_map(f, ho, j, sf, sh, sw);
        else if (ho >= Pp + Hn)     bot_map(f, ho - Pp - Hn, j, sf, sh, sw);
        else { sf = f; sh = ho - Pp; sw = j; }
    } else if (wo < Pp) {
        if (ho < Pp)                top_map(f, ho, 0, sf, sh, sw);
        else if (ho >= Pp + Hn)     bot_map(f, ho - Pp - Hn, 0, sf, sh, sw);
        else                        lft_map(f, ho - Pp, wo, sf, sh, sw);
    } else {
        if (ho < Pp)                top_map(f, ho, Wn - 1, sf, sh, sw);
        else if (ho >= Pp + Hn)     bot_map(f, ho - Pp - Hn, Wn - 1, sf, sh, sw);
        else                        rgt_map(f, ho - Pp, wo - Pp - Wn, sf, sh, sw);
    }
}

__device__ __forceinline__ float gather1(const float* __restrict__ x,
                                         int b, int f, int c, int ho, int wo) {
    int sf, sh, sw;
    src_map(f, ho, wo, sf, sh, sw);
    return x[((size_t)((b * 6 + sf) * Cn + c)) * (Hn * Wn) + sh * Wn + sw];
}

__global__ void __launch_bounds__(256)
cube_pad_fused(const float* __restrict__ x, float4* __restrict__ out4) {
    unsigned tid = blockIdx.x * blockDim.x + threadIdx.x;
    if (tid >= TOTAL4) return;

    unsigned w4  = tid % 33u;          // float4 index within row
    unsigned row = tid / 33u;          // g*OH + ho
    unsigned ho  = row % 132u;
    unsigned g   = row / 132u;         // (b*6+f)*C + c

    float4 v;

    if (ho >= Pp && ho < Pp + Hn && w4 >= 1 && w4 <= 31) {
        // Pure-interior fast path: aligned float2 pair, fully coalesced.
        const float* srow = x + (size_t)g * (Hn * Wn) + (ho - Pp) * Wn;
        float2 a = *(const float2*)(srow + 4 * w4 - 2);
        float2 b = *(const float2*)(srow + 4 * w4);
        v = make_float4(a.x, a.y, b.x, b.y);
    } else {
        // Boundary float4 (pads / halo rows): per-element gather.
        int b_ = g / (6 * Cn);
        int f  = (g / Cn) % 6;
        int c  = g % Cn;
        int wo = w4 * 4;
        v.x = gather1(x, b_, f, c, ho, wo + 0);
        v.y = gather1(x, b_, f, c, ho, wo + 1);
        v.z = gather1(x, b_, f, c, ho, wo + 2);
        v.w = gather1(x, b_, f, c, ho, wo + 3);
    }

    out4[tid] = v;
}

extern "C" void kernel_launch(void* const* d_in, const int* in_sizes, int n_in,
                              void* d_out, int out_size) {
    const float* x = (const float*)d_in[0];
    cube_pad_fused<<<(TOTAL4 + 255) / 256, 256>>>(x, (float4*)d_out);
}

// round 3
// speedup vs baseline: 1.2520x; 1.0543x over previous
#include <cuda_runtime.h>

// CubePadding: x [B=4, 6, C=64, H=128, W=128] f32 -> out [B, 6, C, 132, 132] f32
// Single kernel, block-range split:
//   blocks [0, BND_BLOCKS)         : boundary/halo float4 gathers (latency-bound, overlapped)
//   blocks [BND_BLOCKS, +INT_BLOCKS): interior, warp-per-row, shuffle-realigned float4 copy

#define Pp 2
#define Bn 4
#define Cn 64
#define Hn 128
#define Wn 128
#define OH 132
#define OW 132

#define NG       (Bn * 6 * Cn)            // 1536 face-channels
#define INT_ROWS (NG * Hn)                // 196608 interior rows
#define INT_BLOCKS (INT_ROWS / 8)         // 24576 (8 warps/block, warp-per-row)
#define BND_PER_G (4 * 33 + Hn * 2)       // 388 boundary float4s per g
#define BND_TOTAL (NG * BND_PER_G)        // 595968
#define BND_BLOCKS ((BND_TOTAL + 255) / 256) // 2328

// face ids: 0=back(fb) 1=down(fd) 2=front(ff) 3=left(fl) 4=right(fr) 5=top(ft)

__device__ __forceinline__ void top_map(int f, int i, int j, int& sf, int& sh, int& sw) {
    switch (f) {
        case 0: sf = 5; sh = Pp - 1 - i;  sw = j;           break;
        case 1: sf = 2; sh = Hn - Pp + i; sw = j;           break;
        case 2: sf = 5; sh = Hn - Pp + i; sw = j;           break;
        case 3: sf = 5; sh = j;           sw = i;           break;
        case 4: sf = 5; sh = j;           sw = Wn - 1 - i;  break;
        default: sf = 0; sh = Pp - 1 - i; sw = j;           break;
    }
}

__device__ __forceinline__ void bot_map(int f, int i, int j, int& sf, int& sh, int& sw) {
    switch (f) {
        case 0: sf = 1; sh = Hn - 1 - i;  sw = j;           break;
        case 1: sf = 0; sh = Hn - 1 - i;  sw = j;           break;
        case 2: sf = 1; sh = i;           sw = j;           break;
        case 3: sf = 1; sh = j;           sw = Pp - 1 - i;  break;
        case 4: sf = 1; sh = j;           sw = Wn - Pp + i; break;
        default: sf = 2; sh = i;          sw = j;           break;
    }
}

__device__ __forceinline__ void lft_map(int f, int r, int i, int& sf, int& sh, int& sw) {
    switch (f) {
        case 0: sf = 4; sh = r;           sw = Wn - Pp + i; break;
        case 1: sf = 3; sh = Hn - 1 - i;  sw = r;           break;
        case 2: sf = 3; sh = r;           sw = Wn - Pp + i; break;
        case 3: sf = 0; sh = r;           sw = Wn - Pp + i; break;
        case 4: sf = 2; sh = r;           sw = Wn - Pp + i; break;
        default: sf = 3; sh = i;          sw = r;           break;
    }
}

__device__ __forceinline__ void rgt_map(int f, int r, int i, int& sf, int& sh, int& sw) {
    switch (f) {
        case 0: sf = 3; sh = r;           sw = i;           break;
        case 1: sf = 4; sh = Hn - Pp + i; sw = r;           break;
        case 2: sf = 4; sh = r;           sw = i;           break;
        case 3: sf = 2; sh = r;           sw = i;           break;
        case 4: sf = 0; sh = r;           sw = i;           break;
        default: sf = 4; sh = Pp - 1 - i; sw = r;           break;
    }
}

__device__ __forceinline__ void src_map(int f, int ho, int wo, int& sf, int& sh, int& sw) {
    if (wo >= Pp && wo < Pp + Wn) {
        int j = wo - Pp;
        if (ho < Pp)                top_map(f, ho, j, sf, sh, sw);
        else if (ho >= Pp + Hn)     bot_map(f, ho - Pp - Hn, j, sf, sh, sw);
        else { sf = f; sh = ho - Pp; sw = j; }
    } else if (wo < Pp) {
        if (ho < Pp)                top_map(f, ho, 0, sf, sh, sw);
        else if (ho >= Pp + Hn)     bot_map(f, ho - Pp - Hn, 0, sf, sh, sw);
        else                        lft_map(f, ho - Pp, wo, sf, sh, sw);
    } else {
        if (ho < Pp)                top_map(f, ho, Wn - 1, sf, sh, sw);
        else if (ho >= Pp + Hn)     bot_map(f, ho - Pp - Hn, Wn - 1, sf, sh, sw);
        else                        rgt_map(f, ho - Pp, wo - Pp - Wn, sf, sh, sw);
    }
}

__device__ __forceinline__ float gather1(const float* __restrict__ x,
                                         int b, int f, int c, int ho, int wo) {
    int sf, sh, sw;
    src_map(f, ho, wo, sf, sh, sw);
    return x[((size_t)((b * 6 + sf) * Cn + c)) * (Hn * Wn) + sh * Wn + sw];
}

__global__ void __launch_bounds__(256)
cube_pad(const float* __restrict__ x, float4* __restrict__ out4) {
    if (blockIdx.x >= BND_BLOCKS) {
        // ---------------- interior: warp-per-row ----------------
        unsigned warp  = threadIdx.x >> 5;
        unsigned lane  = threadIdx.x & 31;
        unsigned row   = (blockIdx.x - BND_BLOCKS) * 8u + warp;   // < INT_ROWS
        unsigned h     = row & (Hn - 1);
        unsigned g     = row >> 7;

        const float4* srow4 = (const float4*)(x + ((size_t)g << 14) + h * Wn);
        float4 a = __ldg(srow4 + lane);          // whole 512B row, aligned, coalesced

        // dst float4 w4 = lane+1 needs src floats [4*lane+2 .. 4*lane+5]
        float nx = __shfl_down_sync(0xffffffffu, a.x, 1);
        float ny = __shfl_down_sync(0xffffffffu, a.y, 1);
        if (lane < 31) {
            float4 v = make_float4(a.z, a.w, nx, ny);
            out4[(size_t)g * (OH * 33) + (h + Pp) * 33 + (lane + 1)] = v;
        }
        return;
    }

    // ---------------- boundary: per-float4 gather ----------------
    unsigned bt = blockIdx.x * 256u + threadIdx.x;
    if (bt >= BND_TOTAL) return;

    unsigned g = bt / BND_PER_G;
    unsigned k = bt - g * BND_PER_G;

    int ho, w4;
    if (k < 132) {                      // full rows ho in {0,1,130,131}
        unsigned r = k / 33u;
        w4 = k - r * 33u;
        ho = (r < 2) ? (int)r : (int)(r + 128);
    } else {                            // interior rows, edge float4s (w4 0 / 32)
        unsigned k2 = k - 132;
        ho = (int)(k2 >> 1) + Pp;
        w4 = (k2 & 1) ? 32 : 0;
    }

    int b_ = g / (6 * Cn);
    int f  = (g / Cn) % 6;
    int c  = g % Cn;
    int wo = w4 * 4;

    float4 v;
    v.x = gather1(x, b_, f, c, ho, wo + 0);
    v.y = gather1(x, b_, f, c, ho, wo + 1);
    v.z = gather1(x, b_, f, c, ho, wo + 2);
    v.w = gather1(x, b_, f, c, ho, wo + 3);

    out4[(size_t)g * (OH * 33) + ho * 33 + w4] = v;
}

extern "C" void kernel_launch(void* const* d_in, const int* in_sizes, int n_in,
                              void* d_out, int out_size) {
    const float* x = (const float*)d_in[0];
    cube_pad<<<BND_BLOCKS + INT_BLOCKS, 256>>>(x, (float4*)d_out);
}

// round 4
// speedup vs baseline: 1.3016x; 1.0395x over previous
#include <cuda_runtime.h>

// CubePadding: x [B=4, 6, C=64, H=128, W=128] f32 -> out [B, 6, C, 132, 132] f32
// Single kernel, block-range split:
//   blocks [0, BND_BLOCKS)          : boundary/halo float4 gathers (latency-bound, overlapped)
//   blocks [BND_BLOCKS, +INT_BLOCKS): interior, warp-per-4-rows, shuffle-realigned float4 copy

#define Pp 2
#define Bn 4
#define Cn 64
#define Hn 128
#define Wn 128
#define OH 132
#define OW 132

#define NG        (Bn * 6 * Cn)               // 1536 face-channels
#define ROWS_PER_WARP 4
#define INT_WARPS (NG * Hn / ROWS_PER_WARP)   // 49152
#define INT_BLOCKS (INT_WARPS / 8)            // 6144 (8 warps/block)
#define BND_PER_G (4 * 33 + Hn * 2)           // 388 boundary float4s per g
#define BND_TOTAL (NG * BND_PER_G)            // 595968
#define BND_BLOCKS ((BND_TOTAL + 255) / 256)  // 2328

// face ids: 0=back(fb) 1=down(fd) 2=front(ff) 3=left(fl) 4=right(fr) 5=top(ft)

__device__ __forceinline__ void top_map(int f, int i, int j, int& sf, int& sh, int& sw) {
    switch (f) {
        case 0: sf = 5; sh = Pp - 1 - i;  sw = j;           break;
        case 1: sf = 2; sh = Hn - Pp + i; sw = j;           break;
        case 2: sf = 5; sh = Hn - Pp + i; sw = j;           break;
        case 3: sf = 5; sh = j;           sw = i;           break;
        case 4: sf = 5; sh = j;           sw = Wn - 1 - i;  break;
        default: sf = 0; sh = Pp - 1 - i; sw = j;           break;
    }
}

__device__ __forceinline__ void bot_map(int f, int i, int j, int& sf, int& sh, int& sw) {
    switch (f) {
        case 0: sf = 1; sh = Hn - 1 - i;  sw = j;           break;
        case 1: sf = 0; sh = Hn - 1 - i;  sw = j;           break;
        case 2: sf = 1; sh = i;           sw = j;           break;
        case 3: sf = 1; sh = j;           sw = Pp - 1 - i;  break;
        case 4: sf = 1; sh = j;           sw = Wn - Pp + i; break;
        default: sf = 2; sh = i;          sw = j;           break;
    }
}

__device__ __forceinline__ void lft_map(int f, int r, int i, int& sf, int& sh, int& sw) {
    switch (f) {
        case 0: sf = 4; sh = r;           sw = Wn - Pp + i; break;
        case 1: sf = 3; sh = Hn - 1 - i;  sw = r;           break;
        case 2: sf = 3; sh = r;           sw = Wn - Pp + i; break;
        case 3: sf = 0; sh = r;           sw = Wn - Pp + i; break;
        case 4: sf = 2; sh = r;           sw = Wn - Pp + i; break;
        default: sf = 3; sh = i;          sw = r;           break;
    }
}

__device__ __forceinline__ void rgt_map(int f, int r, int i, int& sf, int& sh, int& sw) {
    switch (f) {
        case 0: sf = 3; sh = r;           sw = i;           break;
        case 1: sf = 4; sh = Hn - Pp + i; sw = r;           break;
        case 2: sf = 4; sh = r;           sw = i;           break;
        case 3: sf = 2; sh = r;           sw = i;           break;
        case 4: sf = 0; sh = r;           sw = i;           break;
        default: sf = 4; sh = Pp - 1 - i; sw = r;           break;
    }
}

__device__ __forceinline__ void src_map(int f, int ho, int wo, int& sf, int& sh, int& sw) {
    if (wo >= Pp && wo < Pp + Wn) {
        int j = wo - Pp;
        if (ho < Pp)                top_map(f, ho, j, sf, sh, sw);
        else if (ho >= Pp + Hn)     bot_map(f, ho - Pp - Hn, j, sf, sh, sw);
        else { sf = f; sh = ho - Pp; sw = j; }
    } else if (wo < Pp) {
        if (ho < Pp)                top_map(f, ho, 0, sf, sh, sw);
        else if (ho >= Pp + Hn)     bot_map(f, ho - Pp - Hn, 0, sf, sh, sw);
        else                        lft_map(f, ho - Pp, wo, sf, sh, sw);
    } else {
        if (ho < Pp)                top_map(f, ho, Wn - 1, sf, sh, sw);
        else if (ho >= Pp + Hn)     bot_map(f, ho - Pp - Hn, Wn - 1, sf, sh, sw);
        else                        rgt_map(f, ho - Pp, wo - Pp - Wn, sf, sh, sw);
    }
}

__device__ __forceinline__ float gather1(const float* __restrict__ x,
                                         int b, int f, int c, int ho, int wo) {
    int sf, sh, sw;
    src_map(f, ho, wo, sf, sh, sw);
    return __ldg(x + ((size_t)((b * 6 + sf) * Cn + c)) * (Hn * Wn) + sh * Wn + sw);
}

__global__ void __launch_bounds__(256)
cube_pad(const float* __restrict__ x, float4* __restrict__ out4) {
    if (blockIdx.x >= BND_BLOCKS) {
        // ---------------- interior: warp-per-4-rows ----------------
        unsigned warp = threadIdx.x >> 5;
        unsigned lane = threadIdx.x & 31;
        unsigned idx  = (blockIdx.x - BND_BLOCKS) * 8u + warp;   // < INT_WARPS
        unsigned g    = idx >> 5;                                // 32 row-quads per g
        unsigned h0   = (idx & 31u) * ROWS_PER_WARP;

        const float4* src4 = (const float4*)(x + ((size_t)g << 14)) + h0 * (Wn / 4) + lane;
        // 4 independent row loads issued back-to-back (MLP = 4)
        float4 a0 = __ldg(src4);
        float4 a1 = __ldg(src4 + 32);
        float4 a2 = __ldg(src4 + 64);
        float4 a3 = __ldg(src4 + 96);

        float4* dst = out4 + (size_t)g * (OH * 33) + (h0 + Pp) * 33 + (lane + 1);

        float nx, ny;
        nx = __shfl_down_sync(0xffffffffu, a0.x, 1);
        ny = __shfl_down_sync(0xffffffffu, a0.y, 1);
        if (lane < 31) dst[0]      = make_float4(a0.z, a0.w, nx, ny);
        nx = __shfl_down_sync(0xffffffffu, a1.x, 1);
        ny = __shfl_down_sync(0xffffffffu, a1.y, 1);
        if (lane < 31) dst[33]     = make_float4(a1.z, a1.w, nx, ny);
        nx = __shfl_down_sync(0xffffffffu, a2.x, 1);
        ny = __shfl_down_sync(0xffffffffu, a2.y, 1);
        if (lane < 31) dst[66]     = make_float4(a2.z, a2.w, nx, ny);
        nx = __shfl_down_sync(0xffffffffu, a3.x, 1);
        ny = __shfl_down_sync(0xffffffffu, a3.y, 1);
        if (lane < 31) dst[99]     = make_float4(a3.z, a3.w, nx, ny);
        return;
    }

    // ---------------- boundary: per-float4 gather ----------------
    unsigned bt = blockIdx.x * 256u + threadIdx.x;
    if (bt >= BND_TOTAL) return;

    unsigned g = bt / BND_PER_G;
    unsigned k = bt - g * BND_PER_G;

    int ho, w4;
    if (k < 132) {                      // full rows ho in {0,1,130,131}
        unsigned r = k / 33u;
        w4 = k - r * 33u;
        ho = (r < 2) ? (int)r : (int)(r + 128);
    } else {                            // interior rows, edge float4s (w4 0 / 32)
        unsigned k2 = k - 132;
        ho = (int)(k2 >> 1) + Pp;
        w4 = (k2 & 1) ? 32 : 0;
    }

    int b_ = g / (6 * Cn);
    int f  = (g / Cn) % 6;
    int c  = g % Cn;
    int wo = w4 * 4;

    float4 v;
    v.x = gather1(x, b_, f, c, ho, wo + 0);
    v.y = gather1(x, b_, f, c, ho, wo + 1);
    v.z = gather1(x, b_, f, c, ho, wo + 2);
    v.w = gather1(x, b_, f, c, ho, wo + 3);

    out4[(size_t)g * (OH * 33) + ho * 33 + w4] = v;
}

extern "C" void kernel_launch(void* const* d_in, const int* in_sizes, int n_in,
                              void* d_out, int out_size) {
    const float* x = (const float*)d_in[0];
    cube_pad<<<BND_BLOCKS + INT_BLOCKS, 256>>>(x, (float4*)d_out);
}

// round 5
// speedup vs baseline: 1.6604x; 1.2757x over previous
#include <cuda_runtime.h>

// CubePadding: x [B=4, 6, C=64, H=128, W=128] f32 -> out [B, 6, C, 132, 132] f32
// Single kernel. Boundary (halo gather) and interior (streaming copy) blocks are
// interleaved in groups of 353 (97 boundary + 256 interior, exact x24 groups) so
// DRAM stays saturated throughout (no latency-bound prologue/epilogue phase).

#define Pp 2
#define Bn 4
#define Cn 64
#define Hn 128
#define Wn 128
#define OH 132
#define OW 132

#define NG        (Bn * 6 * Cn)               // 1536 face-channels
#define ROWS_PER_WARP 4
#define INT_WARPS (NG * Hn / ROWS_PER_WARP)   // 49152
#define INT_BLOCKS (INT_WARPS / 8)            // 6144
#define BND_PER_G (4 * 33 + Hn * 2)           // 388 boundary float4s per g
#define BND_TOTAL (NG * BND_PER_G)            // 595968 (= 2328 * 256 exactly)
#define BND_BLOCKS (BND_TOTAL / 256)          // 2328
#define GRP_BND   97
#define GRP_INT   256
#define GRP_SIZE  (GRP_BND + GRP_INT)         // 353
#define TOTAL_BLOCKS (INT_BLOCKS + BND_BLOCKS) // 8472 = 24 * 353

// face ids: 0=back(fb) 1=down(fd) 2=front(ff) 3=left(fl) 4=right(fr) 5=top(ft)

__device__ __forceinline__ void top_map(int f, int i, int j, int& sf, int& sh, int& sw) {
    switch (f) {
        case 0: sf = 5; sh = Pp - 1 - i;  sw = j;           break;
        case 1: sf = 2; sh = Hn - Pp + i; sw = j;           break;
        case 2: sf = 5; sh = Hn - Pp + i; sw = j;           break;
        case 3: sf = 5; sh = j;           sw = i;           break;
        case 4: sf = 5; sh = j;           sw = Wn - 1 - i;  break;
        default: sf = 0; sh = Pp - 1 - i; sw = j;           break;
    }
}

__device__ __forceinline__ void bot_map(int f, int i, int j, int& sf, int& sh, int& sw) {
    switch (f) {
        case 0: sf = 1; sh = Hn - 1 - i;  sw = j;           break;
        case 1: sf = 0; sh = Hn - 1 - i;  sw = j;           break;
        case 2: sf = 1; sh = i;           sw = j;           break;
        case 3: sf = 1; sh = j;           sw = Pp - 1 - i;  break;
        case 4: sf = 1; sh = j;           sw = Wn - Pp + i; break;
        default: sf = 2; sh = i;          sw = j;           break;
    }
}

__device__ __forceinline__ void lft_map(int f, int r, int i, int& sf, int& sh, int& sw) {
    switch (f) {
        case 0: sf = 4; sh = r;           sw = Wn - Pp + i; break;
        case 1: sf = 3; sh = Hn - 1 - i;  sw = r;           break;
        case 2: sf = 3; sh = r;           sw = Wn - Pp + i; break;
        case 3: sf = 0; sh = r;           sw = Wn - Pp + i; break;
        case 4: sf = 2; sh = r;           sw = Wn - Pp + i; break;
        default: sf = 3; sh = i;          sw = r;           break;
    }
}

__device__ __forceinline__ void rgt_map(int f, int r, int i, int& sf, int& sh, int& sw) {
    switch (f) {
        case 0: sf = 3; sh = r;           sw = i;           break;
        case 1: sf = 4; sh = Hn - Pp + i; sw = r;           break;
        case 2: sf = 4; sh = r;           sw = i;           break;
        case 3: sf = 2; sh = r;           sw = i;           break;
        case 4: sf = 0; sh = r;           sw = i;           break;
        default: sf = 4; sh = Pp - 1 - i; sw = r;           break;
    }
}

__device__ __forceinline__ void src_map(int f, int ho, int wo, int& sf, int& sh, int& sw) {
    if (wo >= Pp && wo < Pp + Wn) {
        int j = wo - Pp;
        if (ho < Pp)                top_map(f, ho, j, sf, sh, sw);
        else if (ho >= Pp + Hn)     bot_map(f, ho - Pp - Hn, j, sf, sh, sw);
        else { sf = f; sh = ho - Pp; sw = j; }
    } else if (wo < Pp) {
        if (ho < Pp)                top_map(f, ho, 0, sf, sh, sw);
        else if (ho >= Pp + Hn)     bot_map(f, ho - Pp - Hn, 0, sf, sh, sw);
        else                        lft_map(f, ho - Pp, wo, sf, sh, sw);
    } else {
        if (ho < Pp)                top_map(f, ho, Wn - 1, sf, sh, sw);
        else if (ho >= Pp + Hn)     bot_map(f, ho - Pp - Hn, Wn - 1, sf, sh, sw);
        else                        rgt_map(f, ho - Pp, wo - Pp - Wn, sf, sh, sw);
    }
}

__device__ __forceinline__ float gather1(const float* __restrict__ x,
                                         int b, int f, int c, int ho, int wo) {
    int sf, sh, sw;
    src_map(f, ho, wo, sf, sh, sw);
    return __ldg(x + ((size_t)((b * 6 + sf) * Cn + c)) * (Hn * Wn) + sh * Wn + sw);
}

__global__ void __launch_bounds__(256)
cube_pad(const float* __restrict__ x, float4* __restrict__ out4) {
    unsigned grp = blockIdx.x / GRP_SIZE;
    unsigned r   = blockIdx.x - grp * GRP_SIZE;

    if (r >= GRP_BND) {
        // ---------------- interior: warp-per-4-rows ----------------
        unsigned iblk = grp * GRP_INT + (r - GRP_BND);          // < INT_BLOCKS
        unsigned warp = threadIdx.x >> 5;
        unsigned lane = threadIdx.x & 31;
        unsigned idx  = iblk * 8u + warp;                        // < INT_WARPS
        unsigned g    = idx >> 5;                                // 32 row-quads per g
        unsigned h0   = (idx & 31u) * ROWS_PER_WARP;

        const float4* src4 = (const float4*)(x + ((size_t)g << 14)) + h0 * (Wn / 4) + lane;
        float4 a0 = __ldg(src4);
        float4 a1 = __ldg(src4 + 32);
        float4 a2 = __ldg(src4 + 64);
        float4 a3 = __ldg(src4 + 96);

        float4* dst = out4 + (size_t)g * (OH * 33) + (h0 + Pp) * 33 + (lane + 1);

        float nx, ny;
        nx = __shfl_down_sync(0xffffffffu, a0.x, 1);
        ny = __shfl_down_sync(0xffffffffu, a0.y, 1);
        if (lane < 31) dst[0]  = make_float4(a0.z, a0.w, nx, ny);
        nx = __shfl_down_sync(0xffffffffu, a1.x, 1);
        ny = __shfl_down_sync(0xffffffffu, a1.y, 1);
        if (lane < 31) dst[33] = make_float4(a1.z, a1.w, nx, ny);
        nx = __shfl_down_sync(0xffffffffu, a2.x, 1);
        ny = __shfl_down_sync(0xffffffffu, a2.y, 1);
        if (lane < 31) dst[66] = make_float4(a2.z, a2.w, nx, ny);
        nx = __shfl_down_sync(0xffffffffu, a3.x, 1);
        ny = __shfl_down_sync(0xffffffffu, a3.y, 1);
        if (lane < 31) dst[99] = make_float4(a3.z, a3.w, nx, ny);
        return;
    }

    // ---------------- boundary: per-float4 gather ----------------
    unsigned bblk = grp * GRP_BND + r;                           // < BND_BLOCKS
    unsigned bt = bblk * 256u + threadIdx.x;
    if (bt >= BND_TOTAL) return;

    unsigned g = bt / BND_PER_G;
    unsigned k = bt - g * BND_PER_G;

    int ho, w4;
    if (k < 132) {                      // full rows ho in {0,1,130,131}
        unsigned rr = k / 33u;
        w4 = k - rr * 33u;
        ho = (rr < 2) ? (int)rr : (int)(rr + 128);
    } else {                            // interior rows, edge float4s (w4 0 / 32)
        unsigned k2 = k - 132;
        ho = (int)(k2 >> 1) + Pp;
        w4 = (k2 & 1) ? 32 : 0;
    }

    int b_ = g / (6 * Cn);
    int f  = (g / Cn) % 6;
    int c  = g % Cn;
    int wo = w4 * 4;

    float4 v;
    v.x = gather1(x, b_, f, c, ho, wo + 0);
    v.y = gather1(x, b_, f, c, ho, wo + 1);
    v.z = gather1(x, b_, f, c, ho, wo + 2);
    v.w = gather1(x, b_, f, c, ho, wo + 3);

    out4[(size_t)g * (OH * 33) + ho * 33 + w4] = v;
}

extern "C" void kernel_launch(void* const* d_in, const int* in_sizes, int n_in,
                              void* d_out, int out_size) {
    const float* x = (const float*)d_in[0];
    cube_pad<<<TOTAL_BLOCKS, 256>>>(x, (float4*)d_out);
}